// round 13
// baseline (speedup 1.0000x reference)
#include <cuda_runtime.h>
#include <cstdint>

// Problem constants
#define NHEAD   16
#define NGROUP  4
#define HS      64
#define SEQ     2048
#define BATCH   2
#define EDIM    1024
#define QKVN    1536      // 1024 (q) + 256 (k) + 256 (v)
#define MTOT    4096      // BATCH*SEQ
// SM_SCALE * log2(e): folded into Q so softmax uses raw ex2
#define QSCALE  0.18033688011112042f

// Scratch (module-load allocated; no runtime allocation)
__device__ float g_x[(size_t)MTOT * EDIM];      // tf32-rounded x
__device__ float g_wqkv[(size_t)QKVN * EDIM];   // tf32-rounded [Wq;Wk;Wv]
__device__ float g_wo[(size_t)EDIM * EDIM];     // tf32-rounded Wo
__device__ float g_qkv[(size_t)MTOT * QKVN];    // rounded q|k|v per token
__device__ float g_vt[(size_t)BATCH * NGROUP * HS * SEQ];  // V^T fp32 [b][d][s]
__device__ float g_attn[(size_t)MTOT * EDIM];   // rounded attention output

// ---------------- helpers ----------------
__device__ __forceinline__ unsigned f2tf(float x) {
    unsigned r;
    asm("cvt.rna.tf32.f32 %0, %1;" : "=r"(r) : "f"(x));
    return r;
}
__device__ __forceinline__ float tfround(float x) { return __uint_as_float(f2tf(x)); }
__device__ __forceinline__ float ex2f(float x) {
    float r;
    asm("ex2.approx.f32 %0, %1;" : "=f"(r) : "f"(x));
    return r;
}
__device__ __forceinline__ void mma8(float* c, const unsigned* a, const unsigned* b) {
    asm volatile(
        "mma.sync.aligned.m16n8k8.row.col.f32.tf32.tf32.f32 "
        "{%0,%1,%2,%3},{%4,%5,%6,%7},{%8,%9},{%0,%1,%2,%3};\n"
        : "+f"(c[0]), "+f"(c[1]), "+f"(c[2]), "+f"(c[3])
        : "r"(a[0]), "r"(a[1]), "r"(a[2]), "r"(a[3]), "r"(b[0]), "r"(b[1]));
}
__device__ __forceinline__ void ldsm4(unsigned* r, uint32_t addr) {
    asm volatile("ldmatrix.sync.aligned.m8n8.x4.shared.b16 {%0,%1,%2,%3}, [%4];"
                 : "=r"(r[0]), "=r"(r[1]), "=r"(r[2]), "=r"(r[3]) : "r"(addr));
}

// ---------------- cp.async helpers ----------------
__device__ __forceinline__ void cp16(uint32_t dst, const void* src) {
    asm volatile("cp.async.ca.shared.global [%0], [%1], 16;\n" :: "r"(dst), "l"(src));
}
#define CP_COMMIT() asm volatile("cp.async.commit_group;\n" ::: "memory")
#define CP_WAIT1()  asm volatile("cp.async.wait_group 1;\n" ::: "memory")
#define CP_WAIT0()  asm volatile("cp.async.wait_group 0;\n" ::: "memory")

// ---------------- prep: tf32-round x and weights into scratch ----------------
__global__ void __launch_bounds__(256) prep_kernel(
    const float* __restrict__ x,
    const float* __restrict__ Wq, const float* __restrict__ Wk,
    const float* __restrict__ Wv, const float* __restrict__ Wo,
    float* __restrict__ xr, float* __restrict__ wqkv, float* __restrict__ wo)
{
    const int stride = gridDim.x * 256;
    const int i0 = blockIdx.x * 256 + threadIdx.x;
    for (int i = i0; i < MTOT * EDIM; i += stride) xr[i] = tfround(x[i]);
    for (int i = i0; i < QKVN * EDIM; i += stride) {
        int row = i >> 10;
        float v = (row < 1024) ? Wq[i]
                : (row < 1280) ? Wk[i - (1024 << 10)]
                               : Wv[i - (1280 << 10)];
        wqkv[i] = tfround(v);
    }
    for (int i = i0; i < EDIM * EDIM; i += stride) wo[i] = tfround(Wo[i]);
}

// ---------------- V transpose: g_qkv v-section [b][s][256] -> fp32 V^T [b][d][s] ----
__global__ void __launch_bounds__(256) transpose_v(
    const float* __restrict__ qkv, float* __restrict__ vt)
{
    __shared__ float tile[32][33];
    const int tx = threadIdx.x & 31, ty = threadIdx.x >> 5;  // 32x8
    const int s0 = blockIdx.x * 32, d0 = blockIdx.y * 32, b = blockIdx.z;
#pragma unroll
    for (int j = 0; j < 4; j++)
        tile[ty + 8 * j][tx] =
            qkv[((size_t)(b * SEQ + s0 + ty + 8 * j)) * QKVN + EDIM + NGROUP * HS + d0 + tx];
    __syncthreads();
#pragma unroll
    for (int j = 0; j < 4; j++)
        vt[((size_t)(b * NGROUP * HS + d0 + ty + 8 * j)) * SEQ + s0 + tx] =
            tile[tx][ty + 8 * j];
}

// ---------------- GEMM: C = A @ B^T (+bias), tf32 LDSM, BK=16, templated BN ----
// BN_=128: warp tile 32x64 (O-proj). BN_=96: warp tile 32x48 (QKV; better wave fill).
#define BM 128
#define BK 16

template <int BN_>
__global__ void __launch_bounds__(256, 2) gemm_cp(
    const float* __restrict__ A, const float* __restrict__ B,
    const float* __restrict__ bias, float* __restrict__ C,
    int Kdim, int ldc, int round_out)
{
    constexpr int NT = BN_ / 16;   // n-fragments per warp (8 or 6)
    constexpr int NP = BN_ / 32;   // ldsm B pairs (4 or 3)

    __shared__ __align__(16) float smA[3][BM * BK];
    __shared__ __align__(16) float smB[3][BN_ * BK];

    const int tid = threadIdx.x, warp = tid >> 5, lane = tid & 31;
    const int bm = blockIdx.x * BM, bn = blockIdx.y * BN_;
    const int wm = (warp & 3) * 32, wn = (warp >> 2) * (BN_ / 2);

    float acc[2][NT][4];
#pragma unroll
    for (int mt = 0; mt < 2; mt++)
#pragma unroll
        for (int nt = 0; nt < NT; nt++)
#pragma unroll
            for (int r = 0; r < 4; r++) acc[mt][nt][r] = 0.f;

    const int lr = tid >> 2, lg = tid & 3;
    const float* a0 = A + (size_t)(bm + lr) * Kdim + 4 * lg;
    const float* a1 = A + (size_t)(bm + lr + 64) * Kdim + 4 * lg;
    const float* b0 = B + (size_t)(bn + lr) * Kdim + 4 * lg;
    const float* b1 = B + (size_t)(bn + lr + 64) * Kdim + 4 * lg;
    const bool hasB1 = (BN_ == 128) || (lr < BN_ - 64);
    const uint32_t doff = lr * BK + 4 * (lg ^ ((lr >> 1) & 3));
    const uint32_t dB0 = 4 * doff, dB1 = 4 * (doff + 64 * BK);
    const uint32_t saddr = (uint32_t)__cvta_generic_to_shared(&smA[0][0]);
    const uint32_t baddr = (uint32_t)__cvta_generic_to_shared(&smB[0][0]);

    uint32_t offA[2][2];
#pragma unroll
    for (int mt = 0; mt < 2; mt++)
#pragma unroll
        for (int ks = 0; ks < 2; ks++) {
            int row = wm + mt * 16 + (lane & 15);
            int c = 2 * ks + (lane >> 4);
            offA[mt][ks] = 4 * (row * BK + 4 * (c ^ ((row >> 1) & 3)));
        }
    uint32_t offB[NP][2];
#pragma unroll
    for (int p = 0; p < NP; p++)
#pragma unroll
        for (int ks = 0; ks < 2; ks++) {
            int row = wn + p * 16 + (lane & 7) + ((lane & 16) ? 8 : 0);
            int c = 2 * ks + ((lane >> 3) & 1);
            offB[p][ks] = 4 * (row * BK + 4 * (c ^ ((row >> 1) & 3)));
        }

    const int ntiles = Kdim / BK;
#pragma unroll
    for (int p = 0; p < 2; p++) {
        uint32_t sA = saddr + p * (BM * BK * 4);
        uint32_t sB = baddr + p * (BN_ * BK * 4);
        int kb = p * BK;
        cp16(sA + dB0, a0 + kb); cp16(sA + dB1, a1 + kb);
        cp16(sB + dB0, b0 + kb);
        if (hasB1) cp16(sB + dB1, b1 + kb);
        CP_COMMIT();
    }

    int st = 0;
    for (int t = 0; t < ntiles; t++) {
        CP_WAIT1();
        __syncthreads();
        if (t + 2 < ntiles) {
            int s2 = (st + 2 >= 3) ? st - 1 : st + 2;
            uint32_t sA = saddr + s2 * (BM * BK * 4);
            uint32_t sB = baddr + s2 * (BN_ * BK * 4);
            int kb = (t + 2) * BK;
            cp16(sA + dB0, a0 + kb); cp16(sA + dB1, a1 + kb);
            cp16(sB + dB0, b0 + kb);
            if (hasB1) cp16(sB + dB1, b1 + kb);
        }
        CP_COMMIT();

        const uint32_t sAa = saddr + st * (BM * BK * 4);
        const uint32_t sBa = baddr + st * (BN_ * BK * 4);
#pragma unroll
        for (int ks = 0; ks < 2; ks++) {
            unsigned a[2][4];
            ldsm4(a[0], sAa + offA[0][ks]);
            ldsm4(a[1], sAa + offA[1][ks]);
#pragma unroll
            for (int p = 0; p < NP; p++) {
                unsigned b[4];
                ldsm4(b, sBa + offB[p][ks]);
                mma8(acc[0][2 * p],     a[0], b);
                mma8(acc[0][2 * p + 1], a[0], b + 2);
                mma8(acc[1][2 * p],     a[1], b);
                mma8(acc[1][2 * p + 1], a[1], b + 2);
            }
        }
        st = (st + 1 >= 3) ? 0 : st + 1;
    }

    const int fr = lane >> 2, fc = lane & 3;
#pragma unroll
    for (int mt = 0; mt < 2; mt++) {
#pragma unroll
        for (int nt = 0; nt < NT; nt++) {
            int row = bm + wm + mt * 16 + fr;
            int col = bn + wn + (nt >> 1) * 16 + (nt & 1) * 8 + 2 * fc;
            float b0 = bias ? bias[col] : 0.f;
            float b1 = bias ? bias[col + 1] : 0.f;
            float o0 = acc[mt][nt][0] + b0, o1 = acc[mt][nt][1] + b1;
            float o2 = acc[mt][nt][2] + b0, o3 = acc[mt][nt][3] + b1;
            if (round_out) {
                o0 = tfround(o0); o1 = tfround(o1);
                o2 = tfround(o2); o3 = tfround(o3);
            }
            *reinterpret_cast<float2*>(&C[(size_t)row * ldc + col]) = make_float2(o0, o1);
            *reinterpret_cast<float2*>(&C[(size_t)(row + 8) * ldc + col]) = make_float2(o2, o3);
        }
    }
}

// ---------------- Attention: tf32 QK^T/PV, 64-key chunks, 2 stages, lookahead 1 ----
// Per chunk: wait0, sync, issue kc+1 (overlaps all compute), S in two 32-key passes
// (sacc reused), exp+store P per pass, PV over 64 keys. Half the barriers of R12.
// Dynamic smem 96KB: K 2x16KB | V^T 2x16KB | P [128][64] f32 32KB.
#define KSTG 16384

__global__ void __launch_bounds__(128) attn_kernel(
    const float* __restrict__ qkv, const float* __restrict__ vt,
    float* __restrict__ Obuf)
{
    extern __shared__ __align__(16) float pool[];
    const uint32_t kaddr = (uint32_t)__cvta_generic_to_shared(pool);
    const uint32_t vaddr = kaddr + 2 * KSTG;    // +32KB
    const uint32_t paddr = kaddr + 4 * KSTG;    // +64KB

    const int tid = threadIdx.x, warp = tid >> 5, lane = tid & 31;
    const int qb = blockIdx.x, h = blockIdx.y, b = blockIdx.z;
    const int g = h >> 2;

    const float* Qb = qkv + (size_t)b * SEQ * QKVN + h * HS;
    const float* Kb = qkv + (size_t)b * SEQ * QKVN + EDIM + g * HS;
    const float* Vtb = vt + ((size_t)b * NGROUP * HS + g * HS) * SEQ;

    // Stage Q (128x64) into pool[0..8192 floats) with unit-swizzle gg^(r&7)
#pragma unroll
    for (int i = 0; i < 16; i++) {
        int lin = tid + i * 128;
        int r = lin >> 4, gg = lin & 15;
        float4 v = *reinterpret_cast<const float4*>(
            Qb + (size_t)(qb * 128 + r) * QKVN + 4 * gg);
        *reinterpret_cast<float4*>(pool + r * 64 + 4 * (gg ^ (r & 7))) = v;
    }
    __syncthreads();

    const int fr = lane >> 2, fc = lane & 3;

    // Q -> registers once, scaled by SM_SCALE*log2e (softmax uses raw ex2)
    unsigned qh[8][2][4];
#pragma unroll
    for (int ks = 0; ks < 8; ks++)
#pragma unroll
        for (int mt = 0; mt < 2; mt++) {
            int rq = warp * 32 + mt * 16 + fr;   // rq&7 == fr
            qh[ks][mt][0] = f2tf(QSCALE * pool[rq * 64 + 4 * ((2 * ks) ^ fr) + fc]);
            qh[ks][mt][1] = f2tf(QSCALE * pool[(rq + 8) * 64 + 4 * ((2 * ks) ^ fr) + fc]);
            qh[ks][mt][2] = f2tf(QSCALE * pool[rq * 64 + 4 * ((2 * ks + 1) ^ fr) + fc]);
            qh[ks][mt][3] = f2tf(QSCALE * pool[(rq + 8) * 64 + 4 * ((2 * ks + 1) ^ fr) + fc]);
        }
    __syncthreads();   // Q consumed before cp.async overwrites pool

    // LDSM lane-row precompute
    int rowB[4];
#pragma unroll
    for (int p = 0; p < 4; p++) rowB[p] = p * 16 + (lane & 7) + ((lane & 16) ? 8 : 0);
    const int lbB = (lane >> 3) & 1;
    int rowP[2];
    rowP[0] = warp * 32 + (lane & 15);
    rowP[1] = rowP[0] + 16;
    const int lbP = lane >> 4;
    const int rpx = lane & 7;   // rowP & 7 for both tiles

    // prologue: chunk 0 into stage 0 (K: 64 rows x 16 units; V^T: 64 rows x 16 units)
#pragma unroll
    for (int i = 0; i < 8; i++) {
        int idx = tid + i * 128;
        int r = idx >> 4, gg = idx & 15;
        uint32_t sw = (uint32_t)(r * 256 + 16 * (gg ^ (r & 7)));
        cp16(kaddr + sw, Kb + (size_t)r * QKVN + 4 * gg);
        cp16(vaddr + sw, Vtb + (size_t)r * SEQ + 4 * gg);
    }
    CP_COMMIT();

    float oacc[2][8][4];
#pragma unroll
    for (int mt = 0; mt < 2; mt++)
#pragma unroll
        for (int nt = 0; nt < 8; nt++)
#pragma unroll
            for (int r = 0; r < 4; r++) oacc[mt][nt][r] = 0.f;
    float rs[2][2] = {{0.f, 0.f}, {0.f, 0.f}};

    const int nch = SEQ / 64;   // 32
    for (int kc = 0; kc < nch; kc++) {
        CP_WAIT0();            // chunk kc fully arrived
        __syncthreads();       // all warps done with chunk kc-1 -> its stage free

        // issue chunk kc+1 into stage (kc+1)&1 (overlaps all compute of kc)
        if (kc + 1 < nch) {
            int s = (kc + 1) & 1;
            int k0 = (kc + 1) * 64;
#pragma unroll
            for (int i = 0; i < 8; i++) {
                int idx = tid + i * 128;
                int r = idx >> 4, gg = idx & 15;
                uint32_t sw = (uint32_t)(r * 256 + 16 * (gg ^ (r & 7)));
                cp16(kaddr + s * KSTG + sw, Kb + (size_t)(k0 + r) * QKVN + 4 * gg);
                cp16(vaddr + s * KSTG + sw, Vtb + (size_t)r * SEQ + k0 + 4 * gg);
            }
        }
        CP_COMMIT();

        const uint32_t ka = kaddr + (kc & 1) * KSTG;
        const uint32_t va = vaddr + (kc & 1) * KSTG;

        // S + softmax in two 32-key passes (sacc reused)
#pragma unroll
        for (int hh = 0; hh < 2; hh++) {
            float sacc[2][4][4];
#pragma unroll
            for (int mt = 0; mt < 2; mt++)
#pragma unroll
                for (int nt = 0; nt < 4; nt++)
#pragma unroll
                    for (int r = 0; r < 4; r++) sacc[mt][nt][r] = 0.f;

#pragma unroll
            for (int ks = 0; ks < 8; ks++) {
#pragma unroll
                for (int p = 0; p < 2; p++) {
                    unsigned kb4[4];
                    int row = 32 * hh + rowB[p];
                    int c = 2 * ks + lbB;
                    ldsm4(kb4, ka + row * 256 + 16 * (c ^ (rowB[p] & 7)));
                    mma8(sacc[0][2 * p],     qh[ks][0], kb4);
                    mma8(sacc[0][2 * p + 1], qh[ks][0], kb4 + 2);
                    mma8(sacc[1][2 * p],     qh[ks][1], kb4);
                    mma8(sacc[1][2 * p + 1], qh[ks][1], kb4 + 2);
                }
            }

            // p = 2^s; store raw f32 into P cols [32*hh, 32*hh+32), swizzled
#pragma unroll
            for (int mt = 0; mt < 2; mt++) {
                int rA = warp * 32 + mt * 16 + fr;   // rA&7 == fr
#pragma unroll
                for (int nt = 0; nt < 4; nt++) {
                    float p0 = ex2f(sacc[mt][nt][0]);
                    float p1 = ex2f(sacc[mt][nt][1]);
                    float p2 = ex2f(sacc[mt][nt][2]);
                    float p3 = ex2f(sacc[mt][nt][3]);
                    rs[mt][0] += p0 + p1;
                    rs[mt][1] += p2 + p3;
                    int col = 32 * hh + nt * 8 + 2 * fc;
                    int unit = col >> 2, low = col & 3;
                    uint32_t a0 = paddr + rA * 256 + 16 * (unit ^ fr) + 4 * low;
                    uint32_t a1 = paddr + (rA + 8) * 256 + 16 * (unit ^ fr) + 4 * low;
                    asm volatile("st.shared.v2.f32 [%0], {%1, %2};"
                                 :: "r"(a0), "f"(p0), "f"(p1) : "memory");
                    asm volatile("st.shared.v2.f32 [%0], {%1, %2};"
                                 :: "r"(a1), "f"(p2), "f"(p3) : "memory");
                }
            }
        }
        __syncwarp();

        // O += P @ V over 64 keys (8 k8-steps); V^T rows = d, 64-key pitch
#pragma unroll
        for (int ks = 0; ks < 8; ks++) {
            unsigned pa[2][4];
            int u = 2 * ks + lbP;
            ldsm4(pa[0], paddr + rowP[0] * 256 + 16 * (u ^ rpx));
            ldsm4(pa[1], paddr + rowP[1] * 256 + 16 * (u ^ rpx));
#pragma unroll
            for (int p = 0; p < 4; p++) {
                unsigned vb[4];
                int row = rowB[p];
                int uv = 2 * ks + lbB;
                ldsm4(vb, va + row * 256 + 16 * (uv ^ (row & 7)));
                mma8(oacc[0][2 * p],     pa[0], vb);
                mma8(oacc[0][2 * p + 1], pa[0], vb + 2);
                mma8(oacc[1][2 * p],     pa[1], vb);
                mma8(oacc[1][2 * p + 1], pa[1], vb + 2);
            }
        }
        // no trailing barrier: next iteration's wait+sync protects stage reuse
    }

    // Final normalize + write rounded to g_attn [b, s, h*HS + d]
#pragma unroll
    for (int mt = 0; mt < 2; mt++) {
        float r0 = rs[mt][0], r1 = rs[mt][1];
        r0 += __shfl_xor_sync(0xffffffffu, r0, 1);
        r0 += __shfl_xor_sync(0xffffffffu, r0, 2);
        r1 += __shfl_xor_sync(0xffffffffu, r1, 1);
        r1 += __shfl_xor_sync(0xffffffffu, r1, 2);
        const float inv0 = 1.f / r0, inv1 = 1.f / r1;

        const int row0 = qb * 128 + warp * 32 + mt * 16 + fr;
#pragma unroll
        for (int nt = 0; nt < 8; nt++) {
            int d = (nt >> 1) * 16 + (nt & 1) * 8 + 2 * fc;
            size_t o0 = ((size_t)(b * SEQ + row0)) * EDIM + h * HS + d;
            size_t o1 = ((size_t)(b * SEQ + row0 + 8)) * EDIM + h * HS + d;
            *reinterpret_cast<float2*>(&Obuf[o0]) =
                make_float2(tfround(oacc[mt][nt][0] * inv0), tfround(oacc[mt][nt][1] * inv0));
            *reinterpret_cast<float2*>(&Obuf[o1]) =
                make_float2(tfround(oacc[mt][nt][2] * inv1), tfround(oacc[mt][nt][3] * inv1));
        }
    }
}

// ---------------- launch ----------------
#define ATTN_DSM 98304

extern "C" void kernel_launch(void* const* d_in, const int* in_sizes, int n_in,
                              void* d_out, int out_size)
{
    (void)in_sizes; (void)n_in; (void)out_size;
    const float* x  = (const float*)d_in[0];
    const float* Wq = (const float*)d_in[1];
    const float* Wk = (const float*)d_in[2];
    const float* Wv = (const float*)d_in[3];
    const float* Wo = (const float*)d_in[4];
    const float* bo = (const float*)d_in[5];
    float* out = (float*)d_out;

    float *xr, *wqkv, *wo, *qkv, *vt, *attn;
    cudaGetSymbolAddress((void**)&xr, g_x);
    cudaGetSymbolAddress((void**)&wqkv, g_wqkv);
    cudaGetSymbolAddress((void**)&wo, g_wo);
    cudaGetSymbolAddress((void**)&qkv, g_qkv);
    cudaGetSymbolAddress((void**)&vt, g_vt);
    cudaGetSymbolAddress((void**)&attn, g_attn);

    cudaFuncSetAttribute(attn_kernel, cudaFuncAttributeMaxDynamicSharedMemorySize,
                         ATTN_DSM);

    // 0) pre-round x and weights
    prep_kernel<<<1024, 256>>>(x, Wq, Wk, Wv, Wo, xr, wqkv, wo);

    // 1) fused QKV projection, BN=96 for wave fill (epilogue rounds output)
    dim3 g1(MTOT / BM, QKVN / 96);
    gemm_cp<96><<<g1, 256>>>(xr, wqkv, nullptr, qkv, EDIM, QKVN, 1);

    // 1b) transpose V section -> fp32 V^T [b][d][s]
    dim3 gt(SEQ / 32, NGROUP * HS / 32, BATCH);
    transpose_v<<<gt, 256>>>(qkv, vt);

    // 2) attention (epilogue rounds output)
    dim3 ga(SEQ / 128, NHEAD, BATCH);
    attn_kernel<<<ga, 128, ATTN_DSM>>>(qkv, vt, attn);

    // 3) output projection, BN=128 (single wave already; +bias, no rounding)
    dim3 g3(MTOT / BM, EDIM / 128);
    gemm_cp<128><<<g3, 256>>>(attn, wo, bo, out, EDIM, EDIM, 0);
}

// round 14
// speedup vs baseline: 1.1417x; 1.1417x over previous
#include <cuda_runtime.h>
#include <cstdint>

// Problem constants
#define NHEAD   16
#define NGROUP  4
#define HS      64
#define SEQ     2048
#define BATCH   2
#define EDIM    1024
#define QKVN    1536      // 1024 (q) + 256 (k) + 256 (v)
#define MTOT    4096      // BATCH*SEQ
// SM_SCALE * log2(e): folded into Q so softmax uses raw ex2
#define QSCALE  0.18033688011112042f

// Scratch (module-load allocated; no runtime allocation)
__device__ float g_x[(size_t)MTOT * EDIM];      // tf32-rounded x
__device__ float g_wqkv[(size_t)QKVN * EDIM];   // tf32-rounded [Wq;Wk;Wv]
__device__ float g_wo[(size_t)EDIM * EDIM];     // tf32-rounded Wo
__device__ float g_qkv[(size_t)MTOT * QKVN];    // rounded q|k|v per token
__device__ float g_vt[(size_t)BATCH * NGROUP * HS * SEQ];  // V^T fp32 [b][d][s]
__device__ float g_attn[(size_t)MTOT * EDIM];   // rounded attention output

// ---------------- helpers ----------------
__device__ __forceinline__ unsigned f2tf(float x) {
    unsigned r;
    asm("cvt.rna.tf32.f32 %0, %1;" : "=r"(r) : "f"(x));
    return r;
}
__device__ __forceinline__ float tfround(float x) { return __uint_as_float(f2tf(x)); }
__device__ __forceinline__ float ex2f(float x) {
    float r;
    asm("ex2.approx.f32 %0, %1;" : "=f"(r) : "f"(x));
    return r;
}
__device__ __forceinline__ void mma8(float* c, const unsigned* a, const unsigned* b) {
    asm volatile(
        "mma.sync.aligned.m16n8k8.row.col.f32.tf32.tf32.f32 "
        "{%0,%1,%2,%3},{%4,%5,%6,%7},{%8,%9},{%0,%1,%2,%3};\n"
        : "+f"(c[0]), "+f"(c[1]), "+f"(c[2]), "+f"(c[3])
        : "r"(a[0]), "r"(a[1]), "r"(a[2]), "r"(a[3]), "r"(b[0]), "r"(b[1]));
}
__device__ __forceinline__ void ldsm4(unsigned* r, uint32_t addr) {
    asm volatile("ldmatrix.sync.aligned.m8n8.x4.shared.b16 {%0,%1,%2,%3}, [%4];"
                 : "=r"(r[0]), "=r"(r[1]), "=r"(r[2]), "=r"(r[3]) : "r"(addr));
}

// ---------------- cp.async helpers (.cg: L2-only, no L1 fill) ----------------
__device__ __forceinline__ void cp16(uint32_t dst, const void* src) {
    asm volatile("cp.async.cg.shared.global [%0], [%1], 16;\n" :: "r"(dst), "l"(src));
}
#define CP_COMMIT() asm volatile("cp.async.commit_group;\n" ::: "memory")
#define CP_WAIT1()  asm volatile("cp.async.wait_group 1;\n" ::: "memory")

// ---------------- prep: tf32-round x and weights into scratch ----------------
__global__ void __launch_bounds__(256) prep_kernel(
    const float* __restrict__ x,
    const float* __restrict__ Wq, const float* __restrict__ Wk,
    const float* __restrict__ Wv, const float* __restrict__ Wo,
    float* __restrict__ xr, float* __restrict__ wqkv, float* __restrict__ wo)
{
    const int stride = gridDim.x * 256;
    const int i0 = blockIdx.x * 256 + threadIdx.x;
    for (int i = i0; i < MTOT * EDIM; i += stride) xr[i] = tfround(x[i]);
    for (int i = i0; i < QKVN * EDIM; i += stride) {
        int row = i >> 10;
        float v = (row < 1024) ? Wq[i]
                : (row < 1280) ? Wk[i - (1024 << 10)]
                               : Wv[i - (1280 << 10)];
        wqkv[i] = tfround(v);
    }
    for (int i = i0; i < EDIM * EDIM; i += stride) wo[i] = tfround(Wo[i]);
}

// ---------------- V transpose: g_qkv v-section [b][s][256] -> fp32 V^T [b][d][s] ----
__global__ void __launch_bounds__(256) transpose_v(
    const float* __restrict__ qkv, float* __restrict__ vt)
{
    __shared__ float tile[32][33];
    const int tx = threadIdx.x & 31, ty = threadIdx.x >> 5;  // 32x8
    const int s0 = blockIdx.x * 32, d0 = blockIdx.y * 32, b = blockIdx.z;
#pragma unroll
    for (int j = 0; j < 4; j++)
        tile[ty + 8 * j][tx] =
            qkv[((size_t)(b * SEQ + s0 + ty + 8 * j)) * QKVN + EDIM + NGROUP * HS + d0 + tx];
    __syncthreads();
#pragma unroll
    for (int j = 0; j < 4; j++)
        vt[((size_t)(b * NGROUP * HS + d0 + ty + 8 * j)) * SEQ + s0 + tx] =
            tile[tx][ty + 8 * j];
}

// ---------------- GEMM (R7/R10/R12 proven): C = A @ B^T (+bias), tf32 LDSM, BK=16 ----
#define BM 128
#define BN 128
#define BK 16

__global__ void __launch_bounds__(256, 2) gemm_cp(
    const float* __restrict__ A, const float* __restrict__ B,
    const float* __restrict__ bias, float* __restrict__ C,
    int Kdim, int ldc, int round_out)
{
    __shared__ __align__(16) float smA[3][BM * BK];
    __shared__ __align__(16) float smB[3][BN * BK];

    const int tid = threadIdx.x, warp = tid >> 5, lane = tid & 31;
    const int bm = blockIdx.x * BM, bn = blockIdx.y * BN;
    const int wm = (warp & 3) * 32, wn = (warp >> 2) * 64;

    float acc[2][8][4];
#pragma unroll
    for (int mt = 0; mt < 2; mt++)
#pragma unroll
        for (int nt = 0; nt < 8; nt++)
#pragma unroll
            for (int r = 0; r < 4; r++) acc[mt][nt][r] = 0.f;

    const int lr = tid >> 2, lg = tid & 3;
    const float* a0 = A + (size_t)(bm + lr) * Kdim + 4 * lg;
    const float* a1 = A + (size_t)(bm + lr + 64) * Kdim + 4 * lg;
    const float* b0 = B + (size_t)(bn + lr) * Kdim + 4 * lg;
    const float* b1 = B + (size_t)(bn + lr + 64) * Kdim + 4 * lg;
    const uint32_t doff = lr * BK + 4 * (lg ^ ((lr >> 1) & 3));
    const uint32_t dB0 = 4 * doff, dB1 = 4 * (doff + 64 * BK);
    const uint32_t saddr = (uint32_t)__cvta_generic_to_shared(&smA[0][0]);
    const uint32_t baddr = (uint32_t)__cvta_generic_to_shared(&smB[0][0]);

    uint32_t offA[2][2];
#pragma unroll
    for (int mt = 0; mt < 2; mt++)
#pragma unroll
        for (int ks = 0; ks < 2; ks++) {
            int row = wm + mt * 16 + (lane & 15);
            int c = 2 * ks + (lane >> 4);
            offA[mt][ks] = 4 * (row * BK + 4 * (c ^ ((row >> 1) & 3)));
        }
    uint32_t offB[4][2];
#pragma unroll
    for (int p = 0; p < 4; p++)
#pragma unroll
        for (int ks = 0; ks < 2; ks++) {
            int row = wn + p * 16 + (lane & 7) + ((lane & 16) ? 8 : 0);
            int c = 2 * ks + ((lane >> 3) & 1);
            offB[p][ks] = 4 * (row * BK + 4 * (c ^ ((row >> 1) & 3)));
        }

    const int ntiles = Kdim / BK;
#pragma unroll
    for (int p = 0; p < 2; p++) {
        uint32_t sA = saddr + p * (BM * BK * 4);
        uint32_t sB = baddr + p * (BN * BK * 4);
        int kb = p * BK;
        cp16(sA + dB0, a0 + kb); cp16(sA + dB1, a1 + kb);
        cp16(sB + dB0, b0 + kb); cp16(sB + dB1, b1 + kb);
        CP_COMMIT();
    }

    int st = 0;
    for (int t = 0; t < ntiles; t++) {
        CP_WAIT1();
        __syncthreads();
        if (t + 2 < ntiles) {
            int s2 = (st + 2 >= 3) ? st - 1 : st + 2;
            uint32_t sA = saddr + s2 * (BM * BK * 4);
            uint32_t sB = baddr + s2 * (BN * BK * 4);
            int kb = (t + 2) * BK;
            cp16(sA + dB0, a0 + kb); cp16(sA + dB1, a1 + kb);
            cp16(sB + dB0, b0 + kb); cp16(sB + dB1, b1 + kb);
        }
        CP_COMMIT();

        const uint32_t sAa = saddr + st * (BM * BK * 4);
        const uint32_t sBa = baddr + st * (BN * BK * 4);
#pragma unroll
        for (int ks = 0; ks < 2; ks++) {
            unsigned a[2][4];
            ldsm4(a[0], sAa + offA[0][ks]);
            ldsm4(a[1], sAa + offA[1][ks]);
#pragma unroll
            for (int p = 0; p < 4; p++) {
                unsigned b[4];
                ldsm4(b, sBa + offB[p][ks]);
                mma8(acc[0][2 * p],     a[0], b);
                mma8(acc[0][2 * p + 1], a[0], b + 2);
                mma8(acc[1][2 * p],     a[1], b);
                mma8(acc[1][2 * p + 1], a[1], b + 2);
            }
        }
        st = (st + 1 >= 3) ? 0 : st + 1;
    }

    const int fr = lane >> 2, fc = lane & 3;
#pragma unroll
    for (int mt = 0; mt < 2; mt++) {
#pragma unroll
        for (int nt = 0; nt < 8; nt++) {
            int row = bm + wm + mt * 16 + fr;
            int col = bn + wn + (nt >> 1) * 16 + (nt & 1) * 8 + 2 * fc;
            float b0 = bias ? bias[col] : 0.f;
            float b1 = bias ? bias[col + 1] : 0.f;
            float o0 = acc[mt][nt][0] + b0, o1 = acc[mt][nt][1] + b1;
            float o2 = acc[mt][nt][2] + b0, o3 = acc[mt][nt][3] + b1;
            if (round_out) {
                o0 = tfround(o0); o1 = tfround(o1);
                o2 = tfround(o2); o3 = tfround(o3);
            }
            *reinterpret_cast<float2*>(&C[(size_t)row * ldc + col]) = make_float2(o0, o1);
            *reinterpret_cast<float2*>(&C[(size_t)(row + 8) * ldc + col]) = make_float2(o2, o3);
        }
    }
}

// ---------------- Attention (R12 proven): tf32 QK^T/PV, 3-stage K/V, one barrier/chunk ----
// P stored as raw f32 (MMA truncates to tf32; normalization cancels the bias).
// Dynamic smem 64KB: K 3x8KB | V^T 3x8KB | P 16KB. Q staged over K+V before loop.
__global__ void __launch_bounds__(128) attn_kernel(
    const float* __restrict__ qkv, const float* __restrict__ vt,
    float* __restrict__ Obuf)
{
    extern __shared__ __align__(16) float pool[];
    const uint32_t kaddr = (uint32_t)__cvta_generic_to_shared(pool);
    const uint32_t vaddr = kaddr + 24576;   // + 6144 floats
    const uint32_t paddr = kaddr + 49152;   // + 12288 floats
    float* Ps = pool + 12288;               // [128][32]

    const int tid = threadIdx.x, warp = tid >> 5, lane = tid & 31;
    const int qb = blockIdx.x, h = blockIdx.y, b = blockIdx.z;
    const int g = h >> 2;

    const float* Qb = qkv + (size_t)b * SEQ * QKVN + h * HS;
    const float* Kb = qkv + (size_t)b * SEQ * QKVN + EDIM + g * HS;
    const float* Vtb = vt + ((size_t)b * NGROUP * HS + g * HS) * SEQ;

    // Stage Q (128x64) into pool[0..8192) with chunk-swizzle gg^(r&7)
#pragma unroll
    for (int i = 0; i < 16; i++) {
        int lin = tid + i * 128;
        int r = lin >> 4, gg = lin & 15;
        float4 v = *reinterpret_cast<const float4*>(
            Qb + (size_t)(qb * 128 + r) * QKVN + 4 * gg);
        *reinterpret_cast<float4*>(pool + r * 64 + 4 * (gg ^ (r & 7))) = v;
    }
    __syncthreads();

    const int fr = lane >> 2, fc = lane & 3;

    // Q -> registers once, scaled by SM_SCALE*log2e (softmax uses raw ex2)
    unsigned qh[8][2][4];
#pragma unroll
    for (int ks = 0; ks < 8; ks++)
#pragma unroll
        for (int mt = 0; mt < 2; mt++) {
            int rq = warp * 32 + mt * 16 + fr;   // rq&7 == fr
            qh[ks][mt][0] = f2tf(QSCALE * pool[rq * 64 + 4 * ((2 * ks) ^ fr) + fc]);
            qh[ks][mt][1] = f2tf(QSCALE * pool[(rq + 8) * 64 + 4 * ((2 * ks) ^ fr) + fc]);
            qh[ks][mt][2] = f2tf(QSCALE * pool[rq * 64 + 4 * ((2 * ks + 1) ^ fr) + fc]);
            qh[ks][mt][3] = f2tf(QSCALE * pool[(rq + 8) * 64 + 4 * ((2 * ks + 1) ^ fr) + fc]);
        }
    __syncthreads();   // Q consumed before cp.async overwrites pool

    // LDSM lane-row precompute
    int rowB[4];
#pragma unroll
    for (int p = 0; p < 4; p++) rowB[p] = p * 16 + (lane & 7) + ((lane & 16) ? 8 : 0);
    const int lbB = (lane >> 3) & 1;
    int rowP[2];
    rowP[0] = warp * 32 + (lane & 15);
    rowP[1] = rowP[0] + 16;
    const int lbP = lane >> 4;
    const int rpx = lane & 7;   // rowP & 7 for both tiles

    // prologue: chunks 0 and 1 into stages 0,1
#pragma unroll
    for (int p = 0; p < 2; p++) {
        int k0 = p * 32;
#pragma unroll
        for (int i = 0; i < 4; i++) {
            int idx = tid + i * 128;
            int r = idx >> 4, gg = idx & 15;   // K: 32 rows x 16 chunks of 16B
            cp16(kaddr + p * 8192 + 4 * (r * 64 + 4 * (gg ^ (r & 7))),
                 Kb + (size_t)(k0 + r) * QKVN + 4 * gg);
            int rv = idx >> 3, cv = idx & 7;   // V^T: 64 rows x 8 chunks of 16B
            cp16(vaddr + p * 8192 + 4 * (rv * 32 + 4 * (cv ^ (rv & 7))),
                 Vtb + (size_t)rv * SEQ + k0 + 4 * cv);
        }
        CP_COMMIT();
    }

    float oacc[2][8][4];
#pragma unroll
    for (int mt = 0; mt < 2; mt++)
#pragma unroll
        for (int nt = 0; nt < 8; nt++)
#pragma unroll
            for (int r = 0; r < 4; r++) oacc[mt][nt][r] = 0.f;
    float rs[2][2] = {{0.f, 0.f}, {0.f, 0.f}};

    int st = 0;
    for (int kc = 0; kc < SEQ / 32; kc++) {
        CP_WAIT1();            // chunk kc arrived
        __syncthreads();       // all warps done with chunk kc-1

        const uint32_t ka = kaddr + st * 8192;
        const uint32_t va = vaddr + st * 8192;

        // S = Q @ K^T (tf32): m=2x32 q, n=32 keys, k=64 d
        float sacc[2][4][4];
#pragma unroll
        for (int mt = 0; mt < 2; mt++)
#pragma unroll
            for (int nt = 0; nt < 4; nt++)
#pragma unroll
                for (int r = 0; r < 4; r++) sacc[mt][nt][r] = 0.f;

#pragma unroll
        for (int ks = 0; ks < 8; ks++) {
#pragma unroll
            for (int p = 0; p < 2; p++) {
                unsigned kb4[4];
                int row = rowB[p];
                int c = 2 * ks + lbB;
                ldsm4(kb4, ka + 4 * (row * 64 + 4 * (c ^ (row & 7))));
                mma8(sacc[0][2 * p],     qh[ks][0], kb4);
                mma8(sacc[0][2 * p + 1], qh[ks][0], kb4 + 2);
                mma8(sacc[1][2 * p],     qh[ks][1], kb4);
                mma8(sacc[1][2 * p + 1], qh[ks][1], kb4 + 2);
            }
        }

        // issue chunk kc+2 AFTER S (overlaps tensor drain)
        {
            int s2 = st + 2; if (s2 >= 3) s2 -= 3;
            if (kc + 2 < SEQ / 32) {
                int k0 = (kc + 2) * 32;
#pragma unroll
                for (int i = 0; i < 4; i++) {
                    int idx = tid + i * 128;
                    int r = idx >> 4, gg = idx & 15;
                    cp16(kaddr + s2 * 8192 + 4 * (r * 64 + 4 * (gg ^ (r & 7))),
                         Kb + (size_t)(k0 + r) * QKVN + 4 * gg);
                    int rv = idx >> 3, cv = idx & 7;
                    cp16(vaddr + s2 * 8192 + 4 * (rv * 32 + 4 * (cv ^ (rv & 7))),
                         Vtb + (size_t)rv * SEQ + k0 + 4 * cv);
                }
            }
            CP_COMMIT();
        }

        // softmax + PV in two 16-key halves: exp(h1) overlaps PV(h0) tensor drain
#pragma unroll
        for (int half = 0; half < 2; half++) {
#pragma unroll
            for (int mt = 0; mt < 2; mt++) {
                int rA = warp * 32 + mt * 16 + fr;   // rA&7 == fr
#pragma unroll
                for (int nt2 = 0; nt2 < 2; nt2++) {
                    int nt = 2 * half + nt2;
                    float p0 = ex2f(sacc[mt][nt][0]);
                    float p1 = ex2f(sacc[mt][nt][1]);
                    float p2 = ex2f(sacc[mt][nt][2]);
                    float p3 = ex2f(sacc[mt][nt][3]);
                    rs[mt][0] += p0 + p1;
                    rs[mt][1] += p2 + p3;
                    int col = nt * 8 + 2 * fc;
                    int chunk = col >> 2, word = col & 3;
                    // raw f32 store: MMA truncates to tf32; bias cancels in 1/rowsum
                    *reinterpret_cast<float2*>(
                        &Ps[rA * 32 + 4 * (chunk ^ fr) + word]) = make_float2(p0, p1);
                    *reinterpret_cast<float2*>(
                        &Ps[(rA + 8) * 32 + 4 * (chunk ^ fr) + word]) = make_float2(p2, p3);
                }
            }
            __syncwarp();

            // O += P @ V for this half's 16 keys (k8 steps 2*half, 2*half+1)
#pragma unroll
            for (int ks2 = 0; ks2 < 2; ks2++) {
                int ks = 2 * half + ks2;
                unsigned pa[2][4];
                int c = 2 * ks + lbP;
                ldsm4(pa[0], paddr + 4 * (rowP[0] * 32 + 4 * (c ^ rpx)));
                ldsm4(pa[1], paddr + 4 * (rowP[1] * 32 + 4 * (c ^ rpx)));
#pragma unroll
                for (int p = 0; p < 4; p++) {
                    unsigned vb[4];
                    int row = rowB[p];
                    int cv = 2 * ks + lbB;
                    ldsm4(vb, va + 4 * (row * 32 + 4 * (cv ^ (row & 7))));
                    mma8(oacc[0][2 * p],     pa[0], vb);
                    mma8(oacc[0][2 * p + 1], pa[0], vb + 2);
                    mma8(oacc[1][2 * p],     pa[1], vb);
                    mma8(oacc[1][2 * p + 1], pa[1], vb + 2);
                }
            }
        }
        // no trailing barrier: next iteration's wait+sync protects stage reuse
        st = (st + 1 >= 3) ? 0 : st + 1;
    }

    // Final normalize + write rounded to g_attn [b, s, h*HS + d]
#pragma unroll
    for (int mt = 0; mt < 2; mt++) {
        float r0 = rs[mt][0], r1 = rs[mt][1];
        r0 += __shfl_xor_sync(0xffffffffu, r0, 1);
        r0 += __shfl_xor_sync(0xffffffffu, r0, 2);
        r1 += __shfl_xor_sync(0xffffffffu, r1, 1);
        r1 += __shfl_xor_sync(0xffffffffu, r1, 2);
        const float inv0 = 1.f / r0, inv1 = 1.f / r1;

        const int row0 = qb * 128 + warp * 32 + mt * 16 + fr;
#pragma unroll
        for (int nt = 0; nt < 8; nt++) {
            int d = (nt >> 1) * 16 + (nt & 1) * 8 + 2 * fc;
            size_t o0 = ((size_t)(b * SEQ + row0)) * EDIM + h * HS + d;
            size_t o1 = ((size_t)(b * SEQ + row0 + 8)) * EDIM + h * HS + d;
            *reinterpret_cast<float2*>(&Obuf[o0]) =
                make_float2(tfround(oacc[mt][nt][0] * inv0), tfround(oacc[mt][nt][1] * inv0));
            *reinterpret_cast<float2*>(&Obuf[o1]) =
                make_float2(tfround(oacc[mt][nt][2] * inv1), tfround(oacc[mt][nt][3] * inv1));
        }
    }
}

// ---------------- launch ----------------
#define ATTN_DSM 65536

extern "C" void kernel_launch(void* const* d_in, const int* in_sizes, int n_in,
                              void* d_out, int out_size)
{
    (void)in_sizes; (void)n_in; (void)out_size;
    const float* x  = (const float*)d_in[0];
    const float* Wq = (const float*)d_in[1];
    const float* Wk = (const float*)d_in[2];
    const float* Wv = (const float*)d_in[3];
    const float* Wo = (const float*)d_in[4];
    const float* bo = (const float*)d_in[5];
    float* out = (float*)d_out;

    float *xr, *wqkv, *wo, *qkv, *vt, *attn;
    cudaGetSymbolAddress((void**)&xr, g_x);
    cudaGetSymbolAddress((void**)&wqkv, g_wqkv);
    cudaGetSymbolAddress((void**)&wo, g_wo);
    cudaGetSymbolAddress((void**)&qkv, g_qkv);
    cudaGetSymbolAddress((void**)&vt, g_vt);
    cudaGetSymbolAddress((void**)&attn, g_attn);

    cudaFuncSetAttribute(attn_kernel, cudaFuncAttributeMaxDynamicSharedMemorySize,
                         ATTN_DSM);

    // 0) pre-round x and weights
    prep_kernel<<<1024, 256>>>(x, Wq, Wk, Wv, Wo, xr, wqkv, wo);

    // 1) fused QKV projection (epilogue rounds output)
    dim3 g1(MTOT / BM, QKVN / BN);
    gemm_cp<<<g1, 256>>>(xr, wqkv, nullptr, qkv, EDIM, QKVN, 1);

    // 1b) transpose V section -> fp32 V^T [b][d][s]
    dim3 gt(SEQ / 32, NGROUP * HS / 32, BATCH);
    transpose_v<<<gt, 256>>>(qkv, vt);

    // 2) attention (epilogue rounds output)
    dim3 ga(SEQ / 128, NHEAD, BATCH);
    attn_kernel<<<ga, 128, ATTN_DSM>>>(qkv, vt, attn);

    // 3) output projection (+bias, no rounding)
    dim3 g3(MTOT / BM, EDIM / 128);
    gemm_cp<<<g3, 256>>>(attn, wo, bo, out, EDIM, EDIM, 0);
}

// round 15
// speedup vs baseline: 1.1523x; 1.0093x over previous
#include <cuda_runtime.h>
#include <cstdint>

// Problem constants
#define NHEAD   16
#define NGROUP  4
#define HS      64
#define SEQ     2048
#define BATCH   2
#define EDIM    1024
#define QKVN    1536      // 1024 (q) + 256 (k) + 256 (v)
#define MTOT    4096      // BATCH*SEQ
// SM_SCALE * log2(e): folded into Q so softmax uses raw ex2
#define QSCALE  0.18033688011112042f

// Scratch (module-load allocated; no runtime allocation)
__device__ float g_x[(size_t)MTOT * EDIM];      // tf32-rounded x
__device__ float g_wqkv[(size_t)QKVN * EDIM];   // tf32-rounded [Wq;Wk;Wv]
__device__ float g_wo[(size_t)EDIM * EDIM];     // tf32-rounded Wo
__device__ float g_qkv[(size_t)MTOT * QKVN];    // rounded q|k (v section unused)
__device__ float g_vt[(size_t)BATCH * NGROUP * HS * SEQ];  // V^T fp32 [b][d][s]
__device__ float g_attn[(size_t)MTOT * EDIM];   // rounded attention output

// ---------------- helpers ----------------
__device__ __forceinline__ unsigned f2tf(float x) {
    unsigned r;
    asm("cvt.rna.tf32.f32 %0, %1;" : "=r"(r) : "f"(x));
    return r;
}
__device__ __forceinline__ float tfround(float x) { return __uint_as_float(f2tf(x)); }
__device__ __forceinline__ float ex2f(float x) {
    float r;
    asm("ex2.approx.f32 %0, %1;" : "=f"(r) : "f"(x));
    return r;
}
__device__ __forceinline__ void mma8(float* c, const unsigned* a, const unsigned* b) {
    asm volatile(
        "mma.sync.aligned.m16n8k8.row.col.f32.tf32.tf32.f32 "
        "{%0,%1,%2,%3},{%4,%5,%6,%7},{%8,%9},{%0,%1,%2,%3};\n"
        : "+f"(c[0]), "+f"(c[1]), "+f"(c[2]), "+f"(c[3])
        : "r"(a[0]), "r"(a[1]), "r"(a[2]), "r"(a[3]), "r"(b[0]), "r"(b[1]));
}
__device__ __forceinline__ void ldsm4(unsigned* r, uint32_t addr) {
    asm volatile("ldmatrix.sync.aligned.m8n8.x4.shared.b16 {%0,%1,%2,%3}, [%4];"
                 : "=r"(r[0]), "=r"(r[1]), "=r"(r[2]), "=r"(r[3]) : "r"(addr));
}

// ---------------- cp.async helpers (.cg: L2-only, no L1 fill) ----------------
__device__ __forceinline__ void cp16(uint32_t dst, const void* src) {
    asm volatile("cp.async.cg.shared.global [%0], [%1], 16;\n" :: "r"(dst), "l"(src));
}
#define CP_COMMIT() asm volatile("cp.async.commit_group;\n" ::: "memory")
#define CP_WAIT1()  asm volatile("cp.async.wait_group 1;\n" ::: "memory")

// ---------------- prep: tf32-round x and weights into scratch ----------------
__global__ void __launch_bounds__(256) prep_kernel(
    const float* __restrict__ x,
    const float* __restrict__ Wq, const float* __restrict__ Wk,
    const float* __restrict__ Wv, const float* __restrict__ Wo,
    float* __restrict__ xr, float* __restrict__ wqkv, float* __restrict__ wo)
{
    const int stride = gridDim.x * 256;
    const int i0 = blockIdx.x * 256 + threadIdx.x;
    for (int i = i0; i < MTOT * EDIM; i += stride) xr[i] = tfround(x[i]);
    for (int i = i0; i < QKVN * EDIM; i += stride) {
        int row = i >> 10;
        float v = (row < 1024) ? Wq[i]
                : (row < 1280) ? Wk[i - (1024 << 10)]
                               : Wv[i - (1280 << 10)];
        wqkv[i] = tfround(v);
    }
    for (int i = i0; i < EDIM * EDIM; i += stride) wo[i] = tfround(Wo[i]);
}

// ---------------- GEMM (proven core): C = A @ B^T (+bias), tf32 LDSM, BK=16 ----
// QKV mode: vt_out != nullptr -> V column blocks (bn >= 1280) write directly to
// V^T [b][d][s] (transposed) instead of C, fusing the old transpose_v kernel.
#define BM 128
#define BN 128
#define BK 16
#define VCOL0 (EDIM + NGROUP * HS)   // 1280, block-aligned

__global__ void __launch_bounds__(256, 2) gemm_cp(
    const float* __restrict__ A, const float* __restrict__ B,
    const float* __restrict__ bias, float* __restrict__ C,
    int Kdim, int ldc, int round_out, float* __restrict__ vt_out)
{
    __shared__ __align__(16) float smA[3][BM * BK];
    __shared__ __align__(16) float smB[3][BN * BK];

    const int tid = threadIdx.x, warp = tid >> 5, lane = tid & 31;
    const int bm = blockIdx.x * BM, bn = blockIdx.y * BN;
    const int wm = (warp & 3) * 32, wn = (warp >> 2) * 64;

    float acc[2][8][4];
#pragma unroll
    for (int mt = 0; mt < 2; mt++)
#pragma unroll
        for (int nt = 0; nt < 8; nt++)
#pragma unroll
            for (int r = 0; r < 4; r++) acc[mt][nt][r] = 0.f;

    const int lr = tid >> 2, lg = tid & 3;
    const float* a0 = A + (size_t)(bm + lr) * Kdim + 4 * lg;
    const float* a1 = A + (size_t)(bm + lr + 64) * Kdim + 4 * lg;
    const float* b0 = B + (size_t)(bn + lr) * Kdim + 4 * lg;
    const float* b1 = B + (size_t)(bn + lr + 64) * Kdim + 4 * lg;
    const uint32_t doff = lr * BK + 4 * (lg ^ ((lr >> 1) & 3));
    const uint32_t dB0 = 4 * doff, dB1 = 4 * (doff + 64 * BK);
    const uint32_t saddr = (uint32_t)__cvta_generic_to_shared(&smA[0][0]);
    const uint32_t baddr = (uint32_t)__cvta_generic_to_shared(&smB[0][0]);

    uint32_t offA[2][2];
#pragma unroll
    for (int mt = 0; mt < 2; mt++)
#pragma unroll
        for (int ks = 0; ks < 2; ks++) {
            int row = wm + mt * 16 + (lane & 15);
            int c = 2 * ks + (lane >> 4);
            offA[mt][ks] = 4 * (row * BK + 4 * (c ^ ((row >> 1) & 3)));
        }
    uint32_t offB[4][2];
#pragma unroll
    for (int p = 0; p < 4; p++)
#pragma unroll
        for (int ks = 0; ks < 2; ks++) {
            int row = wn + p * 16 + (lane & 7) + ((lane & 16) ? 8 : 0);
            int c = 2 * ks + ((lane >> 3) & 1);
            offB[p][ks] = 4 * (row * BK + 4 * (c ^ ((row >> 1) & 3)));
        }

    const int ntiles = Kdim / BK;
#pragma unroll
    for (int p = 0; p < 2; p++) {
        uint32_t sA = saddr + p * (BM * BK * 4);
        uint32_t sB = baddr + p * (BN * BK * 4);
        int kb = p * BK;
        cp16(sA + dB0, a0 + kb); cp16(sA + dB1, a1 + kb);
        cp16(sB + dB0, b0 + kb); cp16(sB + dB1, b1 + kb);
        CP_COMMIT();
    }

    int st = 0;
    for (int t = 0; t < ntiles; t++) {
        CP_WAIT1();
        __syncthreads();
        if (t + 2 < ntiles) {
            int s2 = (st + 2 >= 3) ? st - 1 : st + 2;
            uint32_t sA = saddr + s2 * (BM * BK * 4);
            uint32_t sB = baddr + s2 * (BN * BK * 4);
            int kb = (t + 2) * BK;
            cp16(sA + dB0, a0 + kb); cp16(sA + dB1, a1 + kb);
            cp16(sB + dB0, b0 + kb); cp16(sB + dB1, b1 + kb);
        }
        CP_COMMIT();

        const uint32_t sAa = saddr + st * (BM * BK * 4);
        const uint32_t sBa = baddr + st * (BN * BK * 4);
#pragma unroll
        for (int ks = 0; ks < 2; ks++) {
            unsigned a[2][4];
            ldsm4(a[0], sAa + offA[0][ks]);
            ldsm4(a[1], sAa + offA[1][ks]);
#pragma unroll
            for (int p = 0; p < 4; p++) {
                unsigned b[4];
                ldsm4(b, sBa + offB[p][ks]);
                mma8(acc[0][2 * p],     a[0], b);
                mma8(acc[0][2 * p + 1], a[0], b + 2);
                mma8(acc[1][2 * p],     a[1], b);
                mma8(acc[1][2 * p + 1], a[1], b + 2);
            }
        }
        st = (st + 1 >= 3) ? 0 : st + 1;
    }

    const int fr = lane >> 2, fc = lane & 3;
    const bool vmode = (vt_out != nullptr) && (bn >= VCOL0);  // CTA-uniform
#pragma unroll
    for (int mt = 0; mt < 2; mt++) {
#pragma unroll
        for (int nt = 0; nt < 8; nt++) {
            int row = bm + wm + mt * 16 + fr;
            int col = bn + wn + (nt >> 1) * 16 + (nt & 1) * 8 + 2 * fc;
            float b0 = bias ? bias[col] : 0.f;
            float b1 = bias ? bias[col + 1] : 0.f;
            float o0 = acc[mt][nt][0] + b0, o1 = acc[mt][nt][1] + b1;
            float o2 = acc[mt][nt][2] + b0, o3 = acc[mt][nt][3] + b1;
            if (round_out) {
                o0 = tfround(o0); o1 = tfround(o1);
                o2 = tfround(o2); o3 = tfround(o3);
            }
            if (vmode) {
                // write V directly transposed: vt[b*256 + d][s], s = row within batch
                int d = col - VCOL0;
                int bi = row >> 11, s = row & 2047;
                float* vtb = vt_out + ((size_t)(bi * NGROUP * HS + d)) * SEQ;
                vtb[s] = o0;              // (d,   s)
                vtb[SEQ + s] = o1;        // (d+1, s)
                vtb[s + 8] = o2;          // (d,   s+8)
                vtb[SEQ + s + 8] = o3;    // (d+1, s+8)
            } else {
                *reinterpret_cast<float2*>(&C[(size_t)row * ldc + col]) = make_float2(o0, o1);
                *reinterpret_cast<float2*>(&C[(size_t)(row + 8) * ldc + col]) = make_float2(o2, o3);
            }
        }
    }
}

// ---------------- Attention (R12/R14 proven): tf32 QK^T/PV, 3-stage K/V ----------------
// P stored as raw f32 (MMA truncates to tf32; normalization cancels the bias).
// Dynamic smem 64KB: K 3x8KB | V^T 3x8KB | P 16KB. Q staged over K+V before loop.
__global__ void __launch_bounds__(128) attn_kernel(
    const float* __restrict__ qkv, const float* __restrict__ vt,
    float* __restrict__ Obuf)
{
    extern __shared__ __align__(16) float pool[];
    const uint32_t kaddr = (uint32_t)__cvta_generic_to_shared(pool);
    const uint32_t vaddr = kaddr + 24576;   // + 6144 floats
    const uint32_t paddr = kaddr + 49152;   // + 12288 floats
    float* Ps = pool + 12288;               // [128][32]

    const int tid = threadIdx.x, warp = tid >> 5, lane = tid & 31;
    const int qb = blockIdx.x, h = blockIdx.y, b = blockIdx.z;
    const int g = h >> 2;

    const float* Qb = qkv + (size_t)b * SEQ * QKVN + h * HS;
    const float* Kb = qkv + (size_t)b * SEQ * QKVN + EDIM + g * HS;
    const float* Vtb = vt + ((size_t)b * NGROUP * HS + g * HS) * SEQ;

    // Stage Q (128x64) into pool[0..8192) with chunk-swizzle gg^(r&7)
#pragma unroll
    for (int i = 0; i < 16; i++) {
        int lin = tid + i * 128;
        int r = lin >> 4, gg = lin & 15;
        float4 v = *reinterpret_cast<const float4*>(
            Qb + (size_t)(qb * 128 + r) * QKVN + 4 * gg);
        *reinterpret_cast<float4*>(pool + r * 64 + 4 * (gg ^ (r & 7))) = v;
    }
    __syncthreads();

    const int fr = lane >> 2, fc = lane & 3;

    // Q -> registers once, scaled by SM_SCALE*log2e (softmax uses raw ex2)
    unsigned qh[8][2][4];
#pragma unroll
    for (int ks = 0; ks < 8; ks++)
#pragma unroll
        for (int mt = 0; mt < 2; mt++) {
            int rq = warp * 32 + mt * 16 + fr;   // rq&7 == fr
            qh[ks][mt][0] = f2tf(QSCALE * pool[rq * 64 + 4 * ((2 * ks) ^ fr) + fc]);
            qh[ks][mt][1] = f2tf(QSCALE * pool[(rq + 8) * 64 + 4 * ((2 * ks) ^ fr) + fc]);
            qh[ks][mt][2] = f2tf(QSCALE * pool[rq * 64 + 4 * ((2 * ks + 1) ^ fr) + fc]);
            qh[ks][mt][3] = f2tf(QSCALE * pool[(rq + 8) * 64 + 4 * ((2 * ks + 1) ^ fr) + fc]);
        }
    __syncthreads();   // Q consumed before cp.async overwrites pool

    // LDSM lane-row precompute
    int rowB[4];
#pragma unroll
    for (int p = 0; p < 4; p++) rowB[p] = p * 16 + (lane & 7) + ((lane & 16) ? 8 : 0);
    const int lbB = (lane >> 3) & 1;
    int rowP[2];
    rowP[0] = warp * 32 + (lane & 15);
    rowP[1] = rowP[0] + 16;
    const int lbP = lane >> 4;
    const int rpx = lane & 7;   // rowP & 7 for both tiles

    // prologue: chunks 0 and 1 into stages 0,1
#pragma unroll
    for (int p = 0; p < 2; p++) {
        int k0 = p * 32;
#pragma unroll
        for (int i = 0; i < 4; i++) {
            int idx = tid + i * 128;
            int r = idx >> 4, gg = idx & 15;   // K: 32 rows x 16 chunks of 16B
            cp16(kaddr + p * 8192 + 4 * (r * 64 + 4 * (gg ^ (r & 7))),
                 Kb + (size_t)(k0 + r) * QKVN + 4 * gg);
            int rv = idx >> 3, cv = idx & 7;   // V^T: 64 rows x 8 chunks of 16B
            cp16(vaddr + p * 8192 + 4 * (rv * 32 + 4 * (cv ^ (rv & 7))),
                 Vtb + (size_t)rv * SEQ + k0 + 4 * cv);
        }
        CP_COMMIT();
    }

    float oacc[2][8][4];
#pragma unroll
    for (int mt = 0; mt < 2; mt++)
#pragma unroll
        for (int nt = 0; nt < 8; nt++)
#pragma unroll
            for (int r = 0; r < 4; r++) oacc[mt][nt][r] = 0.f;
    float rs[2][2] = {{0.f, 0.f}, {0.f, 0.f}};

    int st = 0;
    for (int kc = 0; kc < SEQ / 32; kc++) {
        CP_WAIT1();            // chunk kc arrived
        __syncthreads();       // all warps done with chunk kc-1

        const uint32_t ka = kaddr + st * 8192;
        const uint32_t va = vaddr + st * 8192;

        // S = Q @ K^T (tf32): m=2x32 q, n=32 keys, k=64 d
        float sacc[2][4][4];
#pragma unroll
        for (int mt = 0; mt < 2; mt++)
#pragma unroll
            for (int nt = 0; nt < 4; nt++)
#pragma unroll
                for (int r = 0; r < 4; r++) sacc[mt][nt][r] = 0.f;

#pragma unroll
        for (int ks = 0; ks < 8; ks++) {
#pragma unroll
            for (int p = 0; p < 2; p++) {
                unsigned kb4[4];
                int row = rowB[p];
                int c = 2 * ks + lbB;
                ldsm4(kb4, ka + 4 * (row * 64 + 4 * (c ^ (row & 7))));
                mma8(sacc[0][2 * p],     qh[ks][0], kb4);
                mma8(sacc[0][2 * p + 1], qh[ks][0], kb4 + 2);
                mma8(sacc[1][2 * p],     qh[ks][1], kb4);
                mma8(sacc[1][2 * p + 1], qh[ks][1], kb4 + 2);
            }
        }

        // issue chunk kc+2 AFTER S (overlaps tensor drain)
        {
            int s2 = st + 2; if (s2 >= 3) s2 -= 3;
            if (kc + 2 < SEQ / 32) {
                int k0 = (kc + 2) * 32;
#pragma unroll
                for (int i = 0; i < 4; i++) {
                    int idx = tid + i * 128;
                    int r = idx >> 4, gg = idx & 15;
                    cp16(kaddr + s2 * 8192 + 4 * (r * 64 + 4 * (gg ^ (r & 7))),
                         Kb + (size_t)(k0 + r) * QKVN + 4 * gg);
                    int rv = idx >> 3, cv = idx & 7;
                    cp16(vaddr + s2 * 8192 + 4 * (rv * 32 + 4 * (cv ^ (rv & 7))),
                         Vtb + (size_t)rv * SEQ + k0 + 4 * cv);
                }
            }
            CP_COMMIT();
        }

        // softmax + PV in two 16-key halves: exp(h1) overlaps PV(h0) tensor drain
#pragma unroll
        for (int half = 0; half < 2; half++) {
#pragma unroll
            for (int mt = 0; mt < 2; mt++) {
                int rA = warp * 32 + mt * 16 + fr;   // rA&7 == fr
#pragma unroll
                for (int nt2 = 0; nt2 < 2; nt2++) {
                    int nt = 2 * half + nt2;
                    float p0 = ex2f(sacc[mt][nt][0]);
                    float p1 = ex2f(sacc[mt][nt][1]);
                    float p2 = ex2f(sacc[mt][nt][2]);
                    float p3 = ex2f(sacc[mt][nt][3]);
                    rs[mt][0] += p0 + p1;
                    rs[mt][1] += p2 + p3;
                    int col = nt * 8 + 2 * fc;
                    int chunk = col >> 2, word = col & 3;
                    // raw f32 store: MMA truncates to tf32; bias cancels in 1/rowsum
                    *reinterpret_cast<float2*>(
                        &Ps[rA * 32 + 4 * (chunk ^ fr) + word]) = make_float2(p0, p1);
                    *reinterpret_cast<float2*>(
                        &Ps[(rA + 8) * 32 + 4 * (chunk ^ fr) + word]) = make_float2(p2, p3);
                }
            }
            __syncwarp();

            // O += P @ V for this half's 16 keys (k8 steps 2*half, 2*half+1)
#pragma unroll
            for (int ks2 = 0; ks2 < 2; ks2++) {
                int ks = 2 * half + ks2;
                unsigned pa[2][4];
                int c = 2 * ks + lbP;
                ldsm4(pa[0], paddr + 4 * (rowP[0] * 32 + 4 * (c ^ rpx)));
                ldsm4(pa[1], paddr + 4 * (rowP[1] * 32 + 4 * (c ^ rpx)));
#pragma unroll
                for (int p = 0; p < 4; p++) {
                    unsigned vb[4];
                    int row = rowB[p];
                    int cv = 2 * ks + lbB;
                    ldsm4(vb, va + 4 * (row * 32 + 4 * (cv ^ (row & 7))));
                    mma8(oacc[0][2 * p],     pa[0], vb);
                    mma8(oacc[0][2 * p + 1], pa[0], vb + 2);
                    mma8(oacc[1][2 * p],     pa[1], vb);
                    mma8(oacc[1][2 * p + 1], pa[1], vb + 2);
                }
            }
        }
        // no trailing barrier: next iteration's wait+sync protects stage reuse
        st = (st + 1 >= 3) ? 0 : st + 1;
    }

    // Final normalize + write rounded to g_attn [b, s, h*HS + d]
#pragma unroll
    for (int mt = 0; mt < 2; mt++) {
        float r0 = rs[mt][0], r1 = rs[mt][1];
        r0 += __shfl_xor_sync(0xffffffffu, r0, 1);
        r0 += __shfl_xor_sync(0xffffffffu, r0, 2);
        r1 += __shfl_xor_sync(0xffffffffu, r1, 1);
        r1 += __shfl_xor_sync(0xffffffffu, r1, 2);
        const float inv0 = 1.f / r0, inv1 = 1.f / r1;

        const int row0 = qb * 128 + warp * 32 + mt * 16 + fr;
#pragma unroll
        for (int nt = 0; nt < 8; nt++) {
            int d = (nt >> 1) * 16 + (nt & 1) * 8 + 2 * fc;
            size_t o0 = ((size_t)(b * SEQ + row0)) * EDIM + h * HS + d;
            size_t o1 = ((size_t)(b * SEQ + row0 + 8)) * EDIM + h * HS + d;
            *reinterpret_cast<float2*>(&Obuf[o0]) =
                make_float2(tfround(oacc[mt][nt][0] * inv0), tfround(oacc[mt][nt][1] * inv0));
            *reinterpret_cast<float2*>(&Obuf[o1]) =
                make_float2(tfround(oacc[mt][nt][2] * inv1), tfround(oacc[mt][nt][3] * inv1));
        }
    }
}

// ---------------- launch ----------------
#define ATTN_DSM 65536

extern "C" void kernel_launch(void* const* d_in, const int* in_sizes, int n_in,
                              void* d_out, int out_size)
{
    (void)in_sizes; (void)n_in; (void)out_size;
    const float* x  = (const float*)d_in[0];
    const float* Wq = (const float*)d_in[1];
    const float* Wk = (const float*)d_in[2];
    const float* Wv = (const float*)d_in[3];
    const float* Wo = (const float*)d_in[4];
    const float* bo = (const float*)d_in[5];
    float* out = (float*)d_out;

    float *xr, *wqkv, *wo, *qkv, *vt, *attn;
    cudaGetSymbolAddress((void**)&xr, g_x);
    cudaGetSymbolAddress((void**)&wqkv, g_wqkv);
    cudaGetSymbolAddress((void**)&wo, g_wo);
    cudaGetSymbolAddress((void**)&qkv, g_qkv);
    cudaGetSymbolAddress((void**)&vt, g_vt);
    cudaGetSymbolAddress((void**)&attn, g_attn);

    cudaFuncSetAttribute(attn_kernel, cudaFuncAttributeMaxDynamicSharedMemorySize,
                         ATTN_DSM);

    // 0) pre-round x and weights
    prep_kernel<<<1024, 256>>>(x, Wq, Wk, Wv, Wo, xr, wqkv, wo);

    // 1) fused QKV projection; V column blocks write directly transposed to vt
    dim3 g1(MTOT / BM, QKVN / BN);
    gemm_cp<<<g1, 256>>>(xr, wqkv, nullptr, qkv, EDIM, QKVN, 1, vt);

    // 2) attention (epilogue rounds output)
    dim3 ga(SEQ / 128, NHEAD, BATCH);
    attn_kernel<<<ga, 128, ATTN_DSM>>>(qkv, vt, attn);

    // 3) output projection (+bias, no rounding)
    dim3 g3(MTOT / BM, EDIM / 128);
    gemm_cp<<<g3, 256>>>(attn, wo, bo, out, EDIM, EDIM, 0, nullptr);
}

// round 16
// speedup vs baseline: 1.1554x; 1.0027x over previous
#include <cuda_runtime.h>
#include <cstdint>

// Problem constants
#define NHEAD   16
#define NGROUP  4
#define HS      64
#define SEQ     2048
#define BATCH   2
#define EDIM    1024
#define QKVN    1536      // 1024 (q) + 256 (k) + 256 (v)
#define MTOT    4096      // BATCH*SEQ
// SM_SCALE * log2(e): folded into Q so softmax uses raw ex2
#define QSCALE  0.18033688011112042f

// Scratch (module-load allocated; no runtime allocation)
__device__ float g_x[(size_t)MTOT * EDIM];      // tf32-rounded x
__device__ float g_wqkv[(size_t)QKVN * EDIM];   // tf32-rounded [Wq;Wk;Wv]
__device__ float g_wo[(size_t)EDIM * EDIM];     // tf32-rounded Wo
__device__ float g_qkv[(size_t)MTOT * QKVN];    // rounded q|k (v section unused)
__device__ float g_vt[(size_t)BATCH * NGROUP * HS * SEQ];  // V^T fp32 [b][d][s]
__device__ float g_attn[(size_t)MTOT * EDIM];   // rounded attention output

// ---------------- helpers ----------------
__device__ __forceinline__ unsigned f2tf(float x) {
    unsigned r;
    asm("cvt.rna.tf32.f32 %0, %1;" : "=r"(r) : "f"(x));
    return r;
}
__device__ __forceinline__ float tfround(float x) { return __uint_as_float(f2tf(x)); }
__device__ __forceinline__ float ex2f(float x) {
    float r;
    asm("ex2.approx.f32 %0, %1;" : "=f"(r) : "f"(x));
    return r;
}
__device__ __forceinline__ void mma8(float* c, const unsigned* a, const unsigned* b) {
    asm volatile(
        "mma.sync.aligned.m16n8k8.row.col.f32.tf32.tf32.f32 "
        "{%0,%1,%2,%3},{%4,%5,%6,%7},{%8,%9},{%0,%1,%2,%3};\n"
        : "+f"(c[0]), "+f"(c[1]), "+f"(c[2]), "+f"(c[3])
        : "r"(a[0]), "r"(a[1]), "r"(a[2]), "r"(a[3]), "r"(b[0]), "r"(b[1]));
}
__device__ __forceinline__ void ldsm4(unsigned* r, uint32_t addr) {
    asm volatile("ldmatrix.sync.aligned.m8n8.x4.shared.b16 {%0,%1,%2,%3}, [%4];"
                 : "=r"(r[0]), "=r"(r[1]), "=r"(r[2]), "=r"(r[3]) : "r"(addr));
}

// ---------------- cp.async helpers (.cg: L2-only, no L1 fill) ----------------
__device__ __forceinline__ void cp16(uint32_t dst, const void* src) {
    asm volatile("cp.async.cg.shared.global [%0], [%1], 16;\n" :: "r"(dst), "l"(src));
}
#define CP_COMMIT() asm volatile("cp.async.commit_group;\n" ::: "memory")
#define CP_WAIT1()  asm volatile("cp.async.wait_group 1;\n" ::: "memory")

// ---------------- prep: tf32-round x and weights into scratch ----------------
__global__ void __launch_bounds__(256) prep_kernel(
    const float* __restrict__ x,
    const float* __restrict__ Wq, const float* __restrict__ Wk,
    const float* __restrict__ Wv, const float* __restrict__ Wo,
    float* __restrict__ xr, float* __restrict__ wqkv, float* __restrict__ wo)
{
    const int stride = gridDim.x * 256;
    const int i0 = blockIdx.x * 256 + threadIdx.x;
    for (int i = i0; i < MTOT * EDIM; i += stride) xr[i] = tfround(x[i]);
    for (int i = i0; i < QKVN * EDIM; i += stride) {
        int row = i >> 10;
        float v = (row < 1024) ? Wq[i]
                : (row < 1280) ? Wk[i - (1024 << 10)]
                               : Wv[i - (1280 << 10)];
        wqkv[i] = tfround(v);
    }
    for (int i = i0; i < EDIM * EDIM; i += stride) wo[i] = tfround(Wo[i]);
}

// ---------------- GEMM (proven core): C = A @ B^T (+bias), tf32 LDSM, BK=16 ----
// QKV mode: vt_out != nullptr -> V column blocks (bn >= 1280) write directly to
// V^T [b][d][s] (transposed) instead of C, fusing the old transpose_v kernel.
#define BM 128
#define BN 128
#define BK 16
#define VCOL0 (EDIM + NGROUP * HS)   // 1280, block-aligned

__global__ void __launch_bounds__(256, 2) gemm_cp(
    const float* __restrict__ A, const float* __restrict__ B,
    const float* __restrict__ bias, float* __restrict__ C,
    int Kdim, int ldc, int round_out, float* __restrict__ vt_out)
{
    __shared__ __align__(16) float smA[3][BM * BK];
    __shared__ __align__(16) float smB[3][BN * BK];

    const int tid = threadIdx.x, warp = tid >> 5, lane = tid & 31;
    const int bm = blockIdx.x * BM, bn = blockIdx.y * BN;
    const int wm = (warp & 3) * 32, wn = (warp >> 2) * 64;

    float acc[2][8][4];
#pragma unroll
    for (int mt = 0; mt < 2; mt++)
#pragma unroll
        for (int nt = 0; nt < 8; nt++)
#pragma unroll
            for (int r = 0; r < 4; r++) acc[mt][nt][r] = 0.f;

    const int lr = tid >> 2, lg = tid & 3;
    const float* a0 = A + (size_t)(bm + lr) * Kdim + 4 * lg;
    const float* a1 = A + (size_t)(bm + lr + 64) * Kdim + 4 * lg;
    const float* b0 = B + (size_t)(bn + lr) * Kdim + 4 * lg;
    const float* b1 = B + (size_t)(bn + lr + 64) * Kdim + 4 * lg;
    const uint32_t doff = lr * BK + 4 * (lg ^ ((lr >> 1) & 3));
    const uint32_t dB0 = 4 * doff, dB1 = 4 * (doff + 64 * BK);
    const uint32_t saddr = (uint32_t)__cvta_generic_to_shared(&smA[0][0]);
    const uint32_t baddr = (uint32_t)__cvta_generic_to_shared(&smB[0][0]);

    uint32_t offA[2][2];
#pragma unroll
    for (int mt = 0; mt < 2; mt++)
#pragma unroll
        for (int ks = 0; ks < 2; ks++) {
            int row = wm + mt * 16 + (lane & 15);
            int c = 2 * ks + (lane >> 4);
            offA[mt][ks] = 4 * (row * BK + 4 * (c ^ ((row >> 1) & 3)));
        }
    uint32_t offB[4][2];
#pragma unroll
    for (int p = 0; p < 4; p++)
#pragma unroll
        for (int ks = 0; ks < 2; ks++) {
            int row = wn + p * 16 + (lane & 7) + ((lane & 16) ? 8 : 0);
            int c = 2 * ks + ((lane >> 3) & 1);
            offB[p][ks] = 4 * (row * BK + 4 * (c ^ ((row >> 1) & 3)));
        }

    const int ntiles = Kdim / BK;
#pragma unroll
    for (int p = 0; p < 2; p++) {
        uint32_t sA = saddr + p * (BM * BK * 4);
        uint32_t sB = baddr + p * (BN * BK * 4);
        int kb = p * BK;
        cp16(sA + dB0, a0 + kb); cp16(sA + dB1, a1 + kb);
        cp16(sB + dB0, b0 + kb); cp16(sB + dB1, b1 + kb);
        CP_COMMIT();
    }

    int st = 0;
    for (int t = 0; t < ntiles; t++) {
        CP_WAIT1();
        __syncthreads();
        if (t + 2 < ntiles) {
            int s2 = (st + 2 >= 3) ? st - 1 : st + 2;
            uint32_t sA = saddr + s2 * (BM * BK * 4);
            uint32_t sB = baddr + s2 * (BN * BK * 4);
            int kb = (t + 2) * BK;
            cp16(sA + dB0, a0 + kb); cp16(sA + dB1, a1 + kb);
            cp16(sB + dB0, b0 + kb); cp16(sB + dB1, b1 + kb);
        }
        CP_COMMIT();

        const uint32_t sAa = saddr + st * (BM * BK * 4);
        const uint32_t sBa = baddr + st * (BN * BK * 4);
#pragma unroll
        for (int ks = 0; ks < 2; ks++) {
            unsigned a[2][4];
            ldsm4(a[0], sAa + offA[0][ks]);
            ldsm4(a[1], sAa + offA[1][ks]);
#pragma unroll
            for (int p = 0; p < 4; p++) {
                unsigned b[4];
                ldsm4(b, sBa + offB[p][ks]);
                mma8(acc[0][2 * p],     a[0], b);
                mma8(acc[0][2 * p + 1], a[0], b + 2);
                mma8(acc[1][2 * p],     a[1], b);
                mma8(acc[1][2 * p + 1], a[1], b + 2);
            }
        }
        st = (st + 1 >= 3) ? 0 : st + 1;
    }

    const int fr = lane >> 2, fc = lane & 3;
    const bool vmode = (vt_out != nullptr) && (bn >= VCOL0);  // CTA-uniform
#pragma unroll
    for (int mt = 0; mt < 2; mt++) {
#pragma unroll
        for (int nt = 0; nt < 8; nt++) {
            int row = bm + wm + mt * 16 + fr;
            int col = bn + wn + (nt >> 1) * 16 + (nt & 1) * 8 + 2 * fc;
            float b0 = bias ? bias[col] : 0.f;
            float b1 = bias ? bias[col + 1] : 0.f;
            float o0 = acc[mt][nt][0] + b0, o1 = acc[mt][nt][1] + b1;
            float o2 = acc[mt][nt][2] + b0, o3 = acc[mt][nt][3] + b1;
            if (round_out) {
                o0 = tfround(o0); o1 = tfround(o1);
                o2 = tfround(o2); o3 = tfround(o3);
            }
            if (vmode) {
                // write V directly transposed: vt[b*256 + d][s], s = row within batch
                int d = col - VCOL0;
                int bi = row >> 11, s = row & 2047;
                float* vtb = vt_out + ((size_t)(bi * NGROUP * HS + d)) * SEQ;
                vtb[s] = o0;              // (d,   s)
                vtb[SEQ + s] = o1;        // (d+1, s)
                vtb[s + 8] = o2;          // (d,   s+8)
                vtb[SEQ + s + 8] = o3;    // (d+1, s+8)
            } else {
                *reinterpret_cast<float2*>(&C[(size_t)row * ldc + col]) = make_float2(o0, o1);
                *reinterpret_cast<float2*>(&C[(size_t)(row + 8) * ldc + col]) = make_float2(o2, o3);
            }
        }
    }
}

// ---------------- Attention: tf32 QK^T/PV, 3-stage K/V, paired-ldsm scheduling ----
// P stored as raw f32 (MMA truncates to tf32; normalization cancels the bias).
// Dynamic smem 64KB: K 3x8KB | V^T 3x8KB | P 16KB. Q staged over K+V before loop.
__global__ void __launch_bounds__(128) attn_kernel(
    const float* __restrict__ qkv, const float* __restrict__ vt,
    float* __restrict__ Obuf)
{
    extern __shared__ __align__(16) float pool[];
    const uint32_t kaddr = (uint32_t)__cvta_generic_to_shared(pool);
    const uint32_t vaddr = kaddr + 24576;   // + 6144 floats
    const uint32_t paddr = kaddr + 49152;   // + 12288 floats
    float* Ps = pool + 12288;               // [128][32]

    const int tid = threadIdx.x, warp = tid >> 5, lane = tid & 31;
    const int qb = blockIdx.x, h = blockIdx.y, b = blockIdx.z;
    const int g = h >> 2;

    const float* Qb = qkv + (size_t)b * SEQ * QKVN + h * HS;
    const float* Kb = qkv + (size_t)b * SEQ * QKVN + EDIM + g * HS;
    const float* Vtb = vt + ((size_t)b * NGROUP * HS + g * HS) * SEQ;

    // Stage Q (128x64) into pool[0..8192) with chunk-swizzle gg^(r&7)
#pragma unroll
    for (int i = 0; i < 16; i++) {
        int lin = tid + i * 128;
        int r = lin >> 4, gg = lin & 15;
        float4 v = *reinterpret_cast<const float4*>(
            Qb + (size_t)(qb * 128 + r) * QKVN + 4 * gg);
        *reinterpret_cast<float4*>(pool + r * 64 + 4 * (gg ^ (r & 7))) = v;
    }
    __syncthreads();

    const int fr = lane >> 2, fc = lane & 3;

    // Q -> registers once, scaled by SM_SCALE*log2e (softmax uses raw ex2)
    unsigned qh[8][2][4];
#pragma unroll
    for (int ks = 0; ks < 8; ks++)
#pragma unroll
        for (int mt = 0; mt < 2; mt++) {
            int rq = warp * 32 + mt * 16 + fr;   // rq&7 == fr
            qh[ks][mt][0] = f2tf(QSCALE * pool[rq * 64 + 4 * ((2 * ks) ^ fr) + fc]);
            qh[ks][mt][1] = f2tf(QSCALE * pool[(rq + 8) * 64 + 4 * ((2 * ks) ^ fr) + fc]);
            qh[ks][mt][2] = f2tf(QSCALE * pool[rq * 64 + 4 * ((2 * ks + 1) ^ fr) + fc]);
            qh[ks][mt][3] = f2tf(QSCALE * pool[(rq + 8) * 64 + 4 * ((2 * ks + 1) ^ fr) + fc]);
        }
    __syncthreads();   // Q consumed before cp.async overwrites pool

    // LDSM lane-row precompute
    int rowB[4];
#pragma unroll
    for (int p = 0; p < 4; p++) rowB[p] = p * 16 + (lane & 7) + ((lane & 16) ? 8 : 0);
    const int lbB = (lane >> 3) & 1;
    int rowP[2];
    rowP[0] = warp * 32 + (lane & 15);
    rowP[1] = rowP[0] + 16;
    const int lbP = lane >> 4;
    const int rpx = lane & 7;   // rowP & 7 for both tiles

    // prologue: chunks 0 and 1 into stages 0,1
#pragma unroll
    for (int p = 0; p < 2; p++) {
        int k0 = p * 32;
#pragma unroll
        for (int i = 0; i < 4; i++) {
            int idx = tid + i * 128;
            int r = idx >> 4, gg = idx & 15;   // K: 32 rows x 16 chunks of 16B
            cp16(kaddr + p * 8192 + 4 * (r * 64 + 4 * (gg ^ (r & 7))),
                 Kb + (size_t)(k0 + r) * QKVN + 4 * gg);
            int rv = idx >> 3, cv = idx & 7;   // V^T: 64 rows x 8 chunks of 16B
            cp16(vaddr + p * 8192 + 4 * (rv * 32 + 4 * (cv ^ (rv & 7))),
                 Vtb + (size_t)rv * SEQ + k0 + 4 * cv);
        }
        CP_COMMIT();
    }

    float oacc[2][8][4];
#pragma unroll
    for (int mt = 0; mt < 2; mt++)
#pragma unroll
        for (int nt = 0; nt < 8; nt++)
#pragma unroll
            for (int r = 0; r < 4; r++) oacc[mt][nt][r] = 0.f;
    float rs[2][2] = {{0.f, 0.f}, {0.f, 0.f}};

    int st = 0;
    for (int kc = 0; kc < SEQ / 32; kc++) {
        CP_WAIT1();            // chunk kc arrived
        __syncthreads();       // all warps done with chunk kc-1

        const uint32_t ka = kaddr + st * 8192;
        const uint32_t va = vaddr + st * 8192;

        // S = Q @ K^T (tf32): m=2x32 q, n=32 keys, k=64 d
        // Paired ldsm: both key-halves' fragments in flight before the MMA burst.
        float sacc[2][4][4];
#pragma unroll
        for (int mt = 0; mt < 2; mt++)
#pragma unroll
            for (int nt = 0; nt < 4; nt++)
#pragma unroll
                for (int r = 0; r < 4; r++) sacc[mt][nt][r] = 0.f;

#pragma unroll
        for (int ks = 0; ks < 8; ks++) {
            unsigned kb0[4], kb1[4];
            int c = 2 * ks + lbB;
            ldsm4(kb0, ka + 4 * (rowB[0] * 64 + 4 * (c ^ (rowB[0] & 7))));
            ldsm4(kb1, ka + 4 * (rowB[1] * 64 + 4 * (c ^ (rowB[1] & 7))));
            mma8(sacc[0][0], qh[ks][0], kb0);
            mma8(sacc[0][1], qh[ks][0], kb0 + 2);
            mma8(sacc[1][0], qh[ks][1], kb0);
            mma8(sacc[1][1], qh[ks][1], kb0 + 2);
            mma8(sacc[0][2], qh[ks][0], kb1);
            mma8(sacc[0][3], qh[ks][0], kb1 + 2);
            mma8(sacc[1][2], qh[ks][1], kb1);
            mma8(sacc[1][3], qh[ks][1], kb1 + 2);
        }

        // issue chunk kc+2 AFTER S (overlaps tensor drain)
        {
            int s2 = st + 2; if (s2 >= 3) s2 -= 3;
            if (kc + 2 < SEQ / 32) {
                int k0 = (kc + 2) * 32;
#pragma unroll
                for (int i = 0; i < 4; i++) {
                    int idx = tid + i * 128;
                    int r = idx >> 4, gg = idx & 15;
                    cp16(kaddr + s2 * 8192 + 4 * (r * 64 + 4 * (gg ^ (r & 7))),
                         Kb + (size_t)(k0 + r) * QKVN + 4 * gg);
                    int rv = idx >> 3, cv = idx & 7;
                    cp16(vaddr + s2 * 8192 + 4 * (rv * 32 + 4 * (cv ^ (rv & 7))),
                         Vtb + (size_t)rv * SEQ + k0 + 4 * cv);
                }
            }
            CP_COMMIT();
        }

        // softmax + PV in two 16-key halves: exp(h1) overlaps PV(h0) tensor drain
#pragma unroll
        for (int half = 0; half < 2; half++) {
#pragma unroll
            for (int mt = 0; mt < 2; mt++) {
                int rA = warp * 32 + mt * 16 + fr;   // rA&7 == fr
#pragma unroll
                for (int nt2 = 0; nt2 < 2; nt2++) {
                    int nt = 2 * half + nt2;
                    float p0 = ex2f(sacc[mt][nt][0]);
                    float p1 = ex2f(sacc[mt][nt][1]);
                    float p2 = ex2f(sacc[mt][nt][2]);
                    float p3 = ex2f(sacc[mt][nt][3]);
                    rs[mt][0] += p0 + p1;
                    rs[mt][1] += p2 + p3;
                    int col = nt * 8 + 2 * fc;
                    int chunk = col >> 2, word = col & 3;
                    // raw f32 store: MMA truncates to tf32; bias cancels in 1/rowsum
                    *reinterpret_cast<float2*>(
                        &Ps[rA * 32 + 4 * (chunk ^ fr) + word]) = make_float2(p0, p1);
                    *reinterpret_cast<float2*>(
                        &Ps[(rA + 8) * 32 + 4 * (chunk ^ fr) + word]) = make_float2(p2, p3);
                }
            }
            __syncwarp();

            // O += P @ V for this half's 16 keys (k8 steps 2*half, 2*half+1)
            // Paired ldsm: pa pair + vb pair in flight before each 8-MMA burst.
#pragma unroll
            for (int ks2 = 0; ks2 < 2; ks2++) {
                int ks = 2 * half + ks2;
                unsigned pa[2][4];
                int c = 2 * ks + lbP;
                ldsm4(pa[0], paddr + 4 * (rowP[0] * 32 + 4 * (c ^ rpx)));
                ldsm4(pa[1], paddr + 4 * (rowP[1] * 32 + 4 * (c ^ rpx)));
                int cv = 2 * ks + lbB;
                unsigned vb0[4], vb1[4];
                ldsm4(vb0, va + 4 * (rowB[0] * 32 + 4 * (cv ^ (rowB[0] & 7))));
                ldsm4(vb1, va + 4 * (rowB[1] * 32 + 4 * (cv ^ (rowB[1] & 7))));
                mma8(oacc[0][0], pa[0], vb0);
                mma8(oacc[0][1], pa[0], vb0 + 2);
                mma8(oacc[1][0], pa[1], vb0);
                mma8(oacc[1][1], pa[1], vb0 + 2);
                mma8(oacc[0][2], pa[0], vb1);
                mma8(oacc[0][3], pa[0], vb1 + 2);
                mma8(oacc[1][2], pa[1], vb1);
                mma8(oacc[1][3], pa[1], vb1 + 2);
                unsigned vb2[4], vb3[4];
                ldsm4(vb2, va + 4 * (rowB[2] * 32 + 4 * (cv ^ (rowB[2] & 7))));
                ldsm4(vb3, va + 4 * (rowB[3] * 32 + 4 * (cv ^ (rowB[3] & 7))));
                mma8(oacc[0][4], pa[0], vb2);
                mma8(oacc[0][5], pa[0], vb2 + 2);
                mma8(oacc[1][4], pa[1], vb2);
                mma8(oacc[1][5], pa[1], vb2 + 2);
                mma8(oacc[0][6], pa[0], vb3);
                mma8(oacc[0][7], pa[0], vb3 + 2);
                mma8(oacc[1][6], pa[1], vb3);
                mma8(oacc[1][7], pa[1], vb3 + 2);
            }
        }
        // no trailing barrier: next iteration's wait+sync protects stage reuse
        st = (st + 1 >= 3) ? 0 : st + 1;
    }

    // Final normalize + write rounded to g_attn [b, s, h*HS + d]
#pragma unroll
    for (int mt = 0; mt < 2; mt++) {
        float r0 = rs[mt][0], r1 = rs[mt][1];
        r0 += __shfl_xor_sync(0xffffffffu, r0, 1);
        r0 += __shfl_xor_sync(0xffffffffu, r0, 2);
        r1 += __shfl_xor_sync(0xffffffffu, r1, 1);
        r1 += __shfl_xor_sync(0xffffffffu, r1, 2);
        const float inv0 = 1.f / r0, inv1 = 1.f / r1;

        const int row0 = qb * 128 + warp * 32 + mt * 16 + fr;
#pragma unroll
        for (int nt = 0; nt < 8; nt++) {
            int d = (nt >> 1) * 16 + (nt & 1) * 8 + 2 * fc;
            size_t o0 = ((size_t)(b * SEQ + row0)) * EDIM + h * HS + d;
            size_t o1 = ((size_t)(b * SEQ + row0 + 8)) * EDIM + h * HS + d;
            *reinterpret_cast<float2*>(&Obuf[o0]) =
                make_float2(tfround(oacc[mt][nt][0] * inv0), tfround(oacc[mt][nt][1] * inv0));
            *reinterpret_cast<float2*>(&Obuf[o1]) =
                make_float2(tfround(oacc[mt][nt][2] * inv1), tfround(oacc[mt][nt][3] * inv1));
        }
    }
}

// ---------------- launch ----------------
#define ATTN_DSM 65536

extern "C" void kernel_launch(void* const* d_in, const int* in_sizes, int n_in,
                              void* d_out, int out_size)
{
    (void)in_sizes; (void)n_in; (void)out_size;
    const float* x  = (const float*)d_in[0];
    const float* Wq = (const float*)d_in[1];
    const float* Wk = (const float*)d_in[2];
    const float* Wv = (const float*)d_in[3];
    const float* Wo = (const float*)d_in[4];
    const float* bo = (const float*)d_in[5];
    float* out = (float*)d_out;

    float *xr, *wqkv, *wo, *qkv, *vt, *attn;
    cudaGetSymbolAddress((void**)&xr, g_x);
    cudaGetSymbolAddress((void**)&wqkv, g_wqkv);
    cudaGetSymbolAddress((void**)&wo, g_wo);
    cudaGetSymbolAddress((void**)&qkv, g_qkv);
    cudaGetSymbolAddress((void**)&vt, g_vt);
    cudaGetSymbolAddress((void**)&attn, g_attn);

    cudaFuncSetAttribute(attn_kernel, cudaFuncAttributeMaxDynamicSharedMemorySize,
                         ATTN_DSM);

    // 0) pre-round x and weights
    prep_kernel<<<1024, 256>>>(x, Wq, Wk, Wv, Wo, xr, wqkv, wo);

    // 1) fused QKV projection; V column blocks write directly transposed to vt
    dim3 g1(MTOT / BM, QKVN / BN);
    gemm_cp<<<g1, 256>>>(xr, wqkv, nullptr, qkv, EDIM, QKVN, 1, vt);

    // 2) attention (epilogue rounds output)
    dim3 ga(SEQ / 128, NHEAD, BATCH);
    attn_kernel<<<ga, 128, ATTN_DSM>>>(qkv, vt, attn);

    // 3) output projection (+bias, no rounding)
    dim3 g3(MTOT / BM, EDIM / 128);
    gemm_cp<<<g3, 256>>>(attn, wo, bo, out, EDIM, EDIM, 0, nullptr);
}